// round 17
// baseline (speedup 1.0000x reference)
#include <cuda_runtime.h>
#include <cuda_bf16.h>
#include <cstdint>

// Problem constants
#define B_TOT   2048
#define N_TOK   98
#define C_DIM   256
#define H_NUM   8
#define HD      32
#define NW      512
#define M_ROWS  (B_TOT * N_TOK)          // 200704
#define QKV_N   (3 * C_DIM)              // 768

// -------- scratch (static device globals; device-code refs ONLY) --------
// Packed format: one uint32 per element = bf16_hi | (bf16_lo << 16).
__device__ uint32_t g_qkv_p[(size_t)M_ROWS * QKV_N];   // 616 MB
__device__ uint32_t g_att_p[(size_t)M_ROWS * C_DIM];   // 205 MB
__device__ float g_bias[H_NUM * N_TOK * N_TOK];

// ================= helpers =================
__device__ __forceinline__ uint32_t smem_u32(const void* p) {
    uint32_t a;
    asm("{ .reg .u64 t; cvta.to.shared.u64 t, %1; cvt.u32.u64 %0, t; }"
        : "=r"(a) : "l"(p));
    return a;
}

__device__ __forceinline__ void mma16816(float* c, const uint32_t* a, const uint32_t* b) {
    asm volatile(
        "mma.sync.aligned.m16n8k16.row.col.f32.bf16.bf16.f32 "
        "{%0,%1,%2,%3}, {%4,%5,%6,%7}, {%8,%9}, {%0,%1,%2,%3};"
        : "+f"(c[0]), "+f"(c[1]), "+f"(c[2]), "+f"(c[3])
        : "r"(a[0]), "r"(a[1]), "r"(a[2]), "r"(a[3]), "r"(b[0]), "r"(b[1]));
}

__device__ __forceinline__ void ldsm4(uint32_t* r, uint32_t addr) {
    asm volatile("ldmatrix.sync.aligned.m8n8.x4.shared.b16 {%0,%1,%2,%3}, [%4];"
                 : "=r"(r[0]), "=r"(r[1]), "=r"(r[2]), "=r"(r[3]) : "r"(addr));
}

__device__ __forceinline__ void split2(float x, float y, uint32_t& hi, uint32_t& lo) {
    __nv_bfloat16 hx = __float2bfloat16(x);
    __nv_bfloat16 hy = __float2bfloat16(y);
    __nv_bfloat16 lx = __float2bfloat16(x - __bfloat162float(hx));
    __nv_bfloat16 ly = __float2bfloat16(y - __bfloat162float(hy));
    hi = (uint32_t)__bfloat16_as_ushort(hx) | ((uint32_t)__bfloat16_as_ushort(hy) << 16);
    lo = (uint32_t)__bfloat16_as_ushort(lx) | ((uint32_t)__bfloat16_as_ushort(ly) << 16);
}

__device__ __forceinline__ uint32_t prmt(uint32_t a, uint32_t b, uint32_t sel) {
    uint32_t d;
    asm("prmt.b32 %0, %1, %2, %3;" : "=r"(d) : "r"(a), "r"(b), "r"(sel));
    return d;
}
#define SEL_HI 0x5410u
#define SEL_LO 0x7632u

__device__ __forceinline__ uint32_t lds32(const char* p) {
    return *reinterpret_cast<const uint32_t*>(p);
}

// ---------------------------------------------------------------
// Kernel 1: gather relative-position bias  -> g_bias[h][n][m]
// ---------------------------------------------------------------
__global__ void gather_bias_kernel(const float* __restrict__ table,
                                   const int* __restrict__ rel) {
    int idx = blockIdx.x * blockDim.x + threadIdx.x;
    const int total = H_NUM * N_TOK * N_TOK;
    if (idx < total) {
        int h  = idx / (N_TOK * N_TOK);
        int nm = idx % (N_TOK * N_TOK);
        g_bias[idx] = table[rel[nm] * H_NUM + h];
    }
}

// ---------------------------------------------------------------
// HMMA bf16x3 split GEMM. Half-chunk compute so the next-buffer STS
// can be issued mid-stream (overlaps the store tail with mma work).
// ---------------------------------------------------------------
#define RB    80          // row bytes (40 halves)
#define REG_B 10240       // region bytes
#define BUF_B 40960       // buffer bytes

// one ks-half (16 of the 32 k-steps) of the proven scalar-LDS chunk
__device__ __forceinline__ void compute_half(const char* sbuf, int wm, int wn,
                                             int lane, int ks, float acc[2][8][4]) {
    const int g = lane >> 2;
    const int t = lane & 3;
    uint32_t ah[2][4], al[2][4];
#pragma unroll
    for (int mt = 0; mt < 2; mt++) {
        const char* a0p = sbuf + (wm + mt * 16 + g) * RB + (ks + 2 * t) * 2;
        ah[mt][0] = lds32(a0p);
        ah[mt][1] = lds32(a0p + 8 * RB);
        ah[mt][2] = lds32(a0p + 16);
        ah[mt][3] = lds32(a0p + 8 * RB + 16);
        al[mt][0] = lds32(a0p + REG_B);
        al[mt][1] = lds32(a0p + REG_B + 8 * RB);
        al[mt][2] = lds32(a0p + REG_B + 16);
        al[mt][3] = lds32(a0p + REG_B + 8 * RB + 16);
    }
#pragma unroll
    for (int qh = 0; qh < 2; qh++) {
        uint32_t bh[4][2], bl[4][2];
#pragma unroll
        for (int q4 = 0; q4 < 4; q4++) {
            const char* b0p = sbuf + 2 * REG_B
                + (wn + (qh * 4 + q4) * 8 + g) * RB + (ks + 2 * t) * 2;
            bh[q4][0] = lds32(b0p);
            bh[q4][1] = lds32(b0p + 16);
            bl[q4][0] = lds32(b0p + REG_B);
            bl[q4][1] = lds32(b0p + REG_B + 16);
        }
#pragma unroll
        for (int q4 = 0; q4 < 4; q4++)
#pragma unroll
            for (int mt = 0; mt < 2; mt++)
                mma16816(acc[mt][qh * 4 + q4], ah[mt], bh[q4]);
#pragma unroll
        for (int q4 = 0; q4 < 4; q4++)
#pragma unroll
            for (int mt = 0; mt < 2; mt++)
                mma16816(acc[mt][qh * 4 + q4], ah[mt], bl[q4]);
#pragma unroll
        for (int q4 = 0; q4 < 4; q4++)
#pragma unroll
            for (int mt = 0; mt < 2; mt++)
                mma16816(acc[mt][qh * 4 + q4], al[mt], bh[q4]);
    }
}

template <bool APACK, bool OPACK>
__device__ __forceinline__ void hgemm_body(char* smem,
                                           const uint32_t* __restrict__ Av,
                                           const float* __restrict__ W,
                                           const float* __restrict__ bias,
                                           void* __restrict__ Cv,
                                           int Ntot) {
    const int tid  = threadIdx.x;
    const int wid  = tid >> 5;
    const int lane = tid & 31;
    const int m0 = blockIdx.y * 128;
    const int n0 = blockIdx.x * 128;
    const int wm = (wid >> 1) * 32;
    const int wn = (wid & 1) * 64;

    float acc[2][8][4];
#pragma unroll
    for (int mt = 0; mt < 2; mt++)
#pragma unroll
        for (int nt = 0; nt < 8; nt++)
#pragma unroll
            for (int j = 0; j < 4; j++) acc[mt][nt][j] = 0.f;

    uint4  ra[4];
    float4 rw[4];

    auto ld = [&](int k0) {
#pragma unroll
        for (int i = 0; i < 4; i++) {
            int f4  = tid + i * 256;
            int row = f4 >> 3;
            int c4  = (f4 & 7) << 2;
            ra[i] = *reinterpret_cast<const uint4*>(Av + (size_t)(m0 + row) * C_DIM + k0 + c4);
            rw[i] = *reinterpret_cast<const float4*>(W + (size_t)(n0 + row) * C_DIM + k0 + c4);
        }
    };
    auto st = [&](char* buf) {
#pragma unroll
        for (int i = 0; i < 4; i++) {
            int f4  = tid + i * 256;
            int row = f4 >> 3;
            int c4  = (f4 & 7) << 2;
            int off = row * RB + c4 * 2;
            uint32_t h01, l01, h23, l23;
            if (APACK) {
                h01 = prmt(ra[i].x, ra[i].y, SEL_HI);
                l01 = prmt(ra[i].x, ra[i].y, SEL_LO);
                h23 = prmt(ra[i].z, ra[i].w, SEL_HI);
                l23 = prmt(ra[i].z, ra[i].w, SEL_LO);
            } else {
                float4 f = *reinterpret_cast<const float4*>(&ra[i]);
                split2(f.x, f.y, h01, l01);
                split2(f.z, f.w, h23, l23);
            }
            *reinterpret_cast<uint2*>(buf + off)         = make_uint2(h01, h23);
            *reinterpret_cast<uint2*>(buf + REG_B + off) = make_uint2(l01, l23);
            split2(rw[i].x, rw[i].y, h01, l01);
            split2(rw[i].z, rw[i].w, h23, l23);
            *reinterpret_cast<uint2*>(buf + 2 * REG_B + off) = make_uint2(h01, h23);
            *reinterpret_cast<uint2*>(buf + 3 * REG_B + off) = make_uint2(l01, l23);
        }
    };

    ld(0);
    st(smem);
    __syncthreads();

#pragma unroll 1
    for (int ch = 0; ch < 8; ch++) {
        const char* buf = smem + (ch & 1) * BUF_B;
        if (ch < 7) ld((ch + 1) * 32);
        compute_half(buf, wm, wn, lane, 0, acc);
        if (ch < 7) st(smem + ((ch + 1) & 1) * BUF_B);   // overlapped with mma
        compute_half(buf, wm, wn, lane, 16, acc);
        __syncthreads();
    }

    const int g = lane >> 2;
    const int t = lane & 3;
    const float f = (OPACK && n0 < 256) ? 0.17677669529663687f : 1.f;
#pragma unroll
    for (int mt = 0; mt < 2; mt++) {
#pragma unroll
        for (int q = 0; q < 8; q++) {
            int rr = m0 + wm + mt * 16 + g;
            int cc = n0 + wn + q * 8 + 2 * t;
            float b0 = bias[cc], b1 = bias[cc + 1];
            float v00 = acc[mt][q][0] + b0, v01 = acc[mt][q][1] + b1;
            float v10 = acc[mt][q][2] + b0, v11 = acc[mt][q][3] + b1;
            if (OPACK) {
                uint32_t hi, lo;
                split2(v00 * f, v01 * f, hi, lo);
                *reinterpret_cast<uint2*>((uint32_t*)Cv + (size_t)rr * Ntot + cc)
                    = make_uint2(prmt(hi, lo, SEL_HI), prmt(hi, lo, SEL_LO));
                split2(v10 * f, v11 * f, hi, lo);
                *reinterpret_cast<uint2*>((uint32_t*)Cv + (size_t)(rr + 8) * Ntot + cc)
                    = make_uint2(prmt(hi, lo, SEL_HI), prmt(hi, lo, SEL_LO));
            } else {
                *reinterpret_cast<float2*>((float*)Cv + (size_t)rr * Ntot + cc)
                    = make_float2(v00, v01);
                *reinterpret_cast<float2*>((float*)Cv + (size_t)(rr + 8) * Ntot + cc)
                    = make_float2(v10, v11);
            }
        }
    }
}

__global__ void __launch_bounds__(256, 2)
qkv_gemm_kernel(const float* __restrict__ x, const float* __restrict__ w,
                const float* __restrict__ b) {
    extern __shared__ char smem[];
    hgemm_body<false, true>(smem, reinterpret_cast<const uint32_t*>(x), w, b,
                            g_qkv_p, QKV_N);
}

__global__ void __launch_bounds__(256, 2)
proj_gemm_kernel(const float* __restrict__ w, const float* __restrict__ b,
                 float* __restrict__ out) {
    extern __shared__ char smem[];
    hgemm_body<true, false>(smem, g_att_p, w, b, out, C_DIM);
}

// ---------------------------------------------------------------
// Kernel 3: HMMA attention, 112-pad, 7 warps, packed inputs
// (R16 verbatim — proven). smem 51200 -> 2 CTAs/SM.
// ---------------------------------------------------------------
#define NP     112
#define REG_B2 (NP * RB)          // 8960
#define VRB2   240
#define VREG2  (HD * VRB2)        // 7680
#define OFF_VT2   (4 * REG_B2)           // 35840
#define ATTN_SMEM (OFF_VT2 + 2 * VREG2)  // 51200
#define ATHREADS  224

__global__ void __launch_bounds__(ATHREADS, 2)
attn_hmma_kernel(const float* __restrict__ mask) {
    extern __shared__ char smem[];
    const int tid  = threadIdx.x;
    const int wid  = tid >> 5;           // 0..6
    const int lane = tid & 31;
    const int g = lane >> 2;
    const int t = lane & 3;
    const int bh = blockIdx.x;
    const int b  = bh >> 3;
    const int h  = bh & 7;

    char*  qk = smem;
    char*  vt = smem + OFF_VT2;
    const uint32_t sb = smem_u32(smem);

    // ---- phase 0: copy packed q,k (PRMT unpack); build V^T ----
#pragma unroll
    for (int i = 0; i < 4; i++) {
        int s = tid + ATHREADS * i;     // 896 slots: 112 rows x 8 quads
        int row = s >> 3;
        int c4  = (s & 7) << 2;
        uint4 qp = make_uint4(0u, 0u, 0u, 0u), kp = qp;
        if (row < N_TOK) {
            size_t base = ((size_t)(b * N_TOK + row)) * QKV_N + h * HD + c4;
            qp = *reinterpret_cast<const uint4*>(g_qkv_p + base);
            kp = *reinterpret_cast<const uint4*>(g_qkv_p + base + C_DIM);
        }
        int off = row * RB + c4 * 2;
        *reinterpret_cast<uint2*>(qk + off)
            = make_uint2(prmt(qp.x, qp.y, SEL_HI), prmt(qp.z, qp.w, SEL_HI));
        *reinterpret_cast<uint2*>(qk + REG_B2 + off)
            = make_uint2(prmt(qp.x, qp.y, SEL_LO), prmt(qp.z, qp.w, SEL_LO));
        *reinterpret_cast<uint2*>(qk + 2 * REG_B2 + off)
            = make_uint2(prmt(kp.x, kp.y, SEL_HI), prmt(kp.z, kp.w, SEL_HI));
        *reinterpret_cast<uint2*>(qk + 3 * REG_B2 + off)
            = make_uint2(prmt(kp.x, kp.y, SEL_LO), prmt(kp.z, kp.w, SEL_LO));
    }
    // V^T: vt[d][token-pair]; 56 token-pairs x 8 d-quads = 448 slots
#pragma unroll
    for (int i = 0; i < 2; i++) {
        int s  = tid + ATHREADS * i;
        int tp = s >> 3;                // 0..55
        int d4 = (s & 7) << 2;
        int t0 = 2 * tp, t1 = 2 * tp + 1;
        uint4 p0 = make_uint4(0u, 0u, 0u, 0u), p1 = p0;
        if (t0 < N_TOK)
            p0 = *reinterpret_cast<const uint4*>(
                g_qkv_p + ((size_t)(b * N_TOK + t0)) * QKV_N + 2 * C_DIM + h * HD + d4);
        if (t1 < N_TOK)
            p1 = *reinterpret_cast<const uint4*>(
                g_qkv_p + ((size_t)(b * N_TOK + t1)) * QKV_N + 2 * C_DIM + h * HD + d4);
        uint32_t e0[4] = { p0.x, p0.y, p0.z, p0.w };
        uint32_t e1[4] = { p1.x, p1.y, p1.z, p1.w };
#pragma unroll
        for (int d = 0; d < 4; d++) {
            *reinterpret_cast<uint32_t*>(vt + (d4 + d) * VRB2 + tp * 4)
                = prmt(e0[d], e1[d], SEL_HI);
            *reinterpret_cast<uint32_t*>(vt + VREG2 + (d4 + d) * VRB2 + tp * 4)
                = prmt(e0[d], e1[d], SEL_LO);
        }
    }
    __syncthreads();   // THE only block-wide sync

    // ---- phase 1: S = q k^T. Warp wid owns rows [wm, wm+16). ----
    const int wm = wid * 16;
    const int arow  = lane & 15;
    const int acol2 = ((lane >> 4) << 3) * 2;
    const int brow  = (lane & 7) + ((lane >> 3) & 2) * 4;
    const int bcol2 = (((lane >> 3) & 1) << 3) * 2;

    float acc[14][4];
#pragma unroll
    for (int q = 0; q < 14; q++)
#pragma unroll
        for (int j = 0; j < 4; j++) acc[q][j] = 0.f;

#pragma unroll
    for (int ks = 0; ks < 32; ks += 16) {
        uint32_t ah[4], al[4];
        uint32_t aaddr = sb + (wm + arow) * RB + ks * 2 + acol2;
        ldsm4(ah, aaddr);
        ldsm4(al, aaddr + REG_B2);
#pragma unroll
        for (int qp = 0; qp < 7; qp++) {
            uint32_t baddr = sb + 2 * REG_B2 + (qp * 16 + brow) * RB + ks * 2 + bcol2;
            uint32_t bh[4], bl[4];
            ldsm4(bh, baddr);
            ldsm4(bl, baddr + REG_B2);
#pragma unroll
            for (int hf = 0; hf < 2; hf++)
                mma16816(acc[qp * 2 + hf], ah, bh + 2 * hf);
#pragma unroll
            for (int hf = 0; hf < 2; hf++)
                mma16816(acc[qp * 2 + hf], ah, bl + 2 * hf);
#pragma unroll
            for (int hf = 0; hf < 2; hf++)
                mma16816(acc[qp * 2 + hf], al, bh + 2 * hf);
        }
    }

    // ---- phase 2: add bias + mask; pad cells = -1e9 ----
    {
        const float* bp = g_bias + (size_t)h * (N_TOK * N_TOK);
        const float* mp = mask + (size_t)(b & (NW - 1)) * (N_TOK * N_TOK);
        const int rr0 = wm + g;
        const int rr1 = rr0 + 8;
#pragma unroll
        for (int q = 0; q < 14; q++) {
            int cc = q * 8 + 2 * t;
            if (cc < N_TOK && rr0 < N_TOK) {
                float2 bb = *reinterpret_cast<const float2*>(bp + rr0 * N_TOK + cc);
                float2 mm = *reinterpret_cast<const float2*>(mp + rr0 * N_TOK + cc);
                acc[q][0] += bb.x + mm.x;
                acc[q][1] += bb.y + mm.y;
            } else {
                acc[q][0] = -1e9f;
                acc[q][1] = -1e9f;
            }
            if (cc < N_TOK && rr1 < N_TOK) {
                float2 bb = *reinterpret_cast<const float2*>(bp + rr1 * N_TOK + cc);
                float2 mm = *reinterpret_cast<const float2*>(mp + rr1 * N_TOK + cc);
                acc[q][2] += bb.x + mm.x;
                acc[q][3] += bb.y + mm.y;
            } else {
                acc[q][2] = -1e9f;
                acc[q][3] = -1e9f;
            }
        }
    }

    // ---- phase 3: warp-local softmax ----
    float inv0, inv1;
    {
        float m0 = -1e30f, m1 = -1e30f;
#pragma unroll
        for (int q = 0; q < 14; q++) {
            m0 = fmaxf(m0, fmaxf(acc[q][0], acc[q][1]));
            m1 = fmaxf(m1, fmaxf(acc[q][2], acc[q][3]));
        }
#pragma unroll
        for (int off = 1; off <= 2; off <<= 1) {
            m0 = fmaxf(m0, __shfl_xor_sync(0xFFFFFFFFu, m0, off));
            m1 = fmaxf(m1, __shfl_xor_sync(0xFFFFFFFFu, m1, off));
        }
        float s0 = 0.f, s1 = 0.f;
#pragma unroll
        for (int q = 0; q < 14; q++) {
            float e0 = __expf(acc[q][0] - m0);
            float e1 = __expf(acc[q][1] - m0);
            float e2 = __expf(acc[q][2] - m1);
            float e3 = __expf(acc[q][3] - m1);
            acc[q][0] = e0; acc[q][1] = e1;
            acc[q][2] = e2; acc[q][3] = e3;
            s0 += e0 + e1;
            s1 += e2 + e3;
        }
#pragma unroll
        for (int off = 1; off <= 2; off <<= 1) {
            s0 += __shfl_xor_sync(0xFFFFFFFFu, s0, off);
            s1 += __shfl_xor_sync(0xFFFFFFFFu, s1, off);
        }
        inv0 = 1.f / s0;
        inv1 = 1.f / s1;
    }

    // ---- phase 4: O = P~ V via mma; A fragments from registers ----
    float oacc[4][4];
#pragma unroll
    for (int nt = 0; nt < 4; nt++)
#pragma unroll
        for (int j = 0; j < 4; j++) oacc[nt][j] = 0.f;

#pragma unroll
    for (int kc = 0; kc < 7; kc++) {
        uint32_t ah[4], al[4];
        split2(acc[2 * kc][0],     acc[2 * kc][1],     ah[0], al[0]);
        split2(acc[2 * kc][2],     acc[2 * kc][3],     ah[1], al[1]);
        split2(acc[2 * kc + 1][0], acc[2 * kc + 1][1], ah[2], al[2]);
        split2(acc[2 * kc + 1][2], acc[2 * kc + 1][3], ah[3], al[3]);
#pragma unroll
        for (int np = 0; np < 2; np++) {
            uint32_t baddr = sb + OFF_VT2 + (np * 16 + brow) * VRB2 + kc * 32 + bcol2;
            uint32_t bh[4], bl[4];
            ldsm4(bh, baddr);
            ldsm4(bl, baddr + VREG2);
#pragma unroll
            for (int hf = 0; hf < 2; hf++) {
                int nt = np * 2 + hf;
                mma16816(oacc[nt], ah, bh + 2 * hf);
                mma16816(oacc[nt], ah, bl + 2 * hf);
                mma16816(oacc[nt], al, bh + 2 * hf);
            }
        }
    }

    // ---- phase 5: normalize + write O packed, rows < 98 ----
    {
        const int rr0 = wm + g;
        const int rr1 = rr0 + 8;
#pragma unroll
        for (int nt = 0; nt < 4; nt++) {
            int cc = h * HD + nt * 8 + 2 * t;
            uint32_t hi, lo;
            if (rr0 < N_TOK) {
                split2(oacc[nt][0] * inv0, oacc[nt][1] * inv0, hi, lo);
                *reinterpret_cast<uint2*>(g_att_p + (size_t)(b * N_TOK + rr0) * C_DIM + cc)
                    = make_uint2(prmt(hi, lo, SEL_HI), prmt(hi, lo, SEL_LO));
            }
            if (rr1 < N_TOK) {
                split2(oacc[nt][2] * inv1, oacc[nt][3] * inv1, hi, lo);
                *reinterpret_cast<uint2*>(g_att_p + (size_t)(b * N_TOK + rr1) * C_DIM + cc)
                    = make_uint2(prmt(hi, lo, SEL_HI), prmt(hi, lo, SEL_LO));
            }
        }
    }
}

// ---------------------------------------------------------------
// Launch
// ---------------------------------------------------------------
extern "C" void kernel_launch(void* const* d_in, const int* in_sizes, int n_in,
                              void* d_out, int out_size) {
    const float* x          = (const float*)d_in[0];
    const float* mask       = (const float*)d_in[1];
    const float* qkv_w      = (const float*)d_in[2];
    const float* qkv_b      = (const float*)d_in[3];
    const float* proj_w     = (const float*)d_in[4];
    const float* proj_b     = (const float*)d_in[5];
    const float* bias_table = (const float*)d_in[6];
    const int*   rel_index  = (const int*)d_in[7];
    float* out = (float*)d_out;

    cudaFuncSetAttribute(attn_hmma_kernel,
                         cudaFuncAttributeMaxDynamicSharedMemorySize, ATTN_SMEM);
    const int gemm_smem = 2 * BUF_B;   // 81920
    cudaFuncSetAttribute(qkv_gemm_kernel,
                         cudaFuncAttributeMaxDynamicSharedMemorySize, gemm_smem);
    cudaFuncSetAttribute(proj_gemm_kernel,
                         cudaFuncAttributeMaxDynamicSharedMemorySize, gemm_smem);

    // 1) bias gather
    {
        int total = H_NUM * N_TOK * N_TOK;
        gather_bias_kernel<<<(total + 255) / 256, 256>>>(bias_table, rel_index);
    }
    // 2) QKV projection (HMMA bf16x3) -> packed g_qkv_p (q prescaled)
    {
        dim3 grid(QKV_N / 128, M_ROWS / 128);
        qkv_gemm_kernel<<<grid, 256, gemm_smem>>>(x, qkv_w, qkv_b);
    }
    // 3) HMMA attention per (b,h), 112-pad, register P + warp softmax
    {
        attn_hmma_kernel<<<B_TOT * H_NUM, ATHREADS, ATTN_SMEM>>>(mask);
    }
    // 4) output projection (HMMA bf16x3, packed A) -> fp32 out
    {
        dim3 grid(C_DIM / 128, M_ROWS / 128);
        proj_gemm_kernel<<<grid, 256, gemm_smem>>>(proj_w, proj_b, out);
    }
}